// round 15
// baseline (speedup 1.0000x reference)
#include <cuda_runtime.h>
#include <stdint.h>

// z[e, :] = h[src[e], :] * h[dst[e], :]
// h: [N=50000, D=64] fp32 (12.8 MB, L2-resident), src/dst: [E=800000] int32,
// out: [E, 64] fp32.
//
// R15: persistent grid-stride variant of the winning R4 body.
// Session-proven config: 8 threads/edge x 2 float4/thread, front-batched
// LDG.128 gathers (4 outstanding), __stcs streaming stores, full-line
// coalescing everywhere. R4 launched 25000 CTAs (~21 waves at occ 8); this
// launches 1184 persistent CTAs (148 SMs x 8) and loops, eliminating
// inter-wave transition overhead and tail imbalance. Body is otherwise
// identical. All other levers (MLP, L1 bypass, TMA store, L2 pinning,
// store policy, 256-bit width) measured and falsified in R5-R13.

static constexpr int D = 64;
static constexpr int VEC_PER_ROW = D / 4;   // 16 float4 per row
static constexpr int THREADS = 256;
static constexpr int EDGES_PER_CTA_ITER = THREADS / 8;  // 32 edges per pass

__global__ void __launch_bounds__(THREADS, 8) u_mul_v_kernel(
    const float4* __restrict__ h,        // [N, 16] as float4
    const int* __restrict__ src,         // [E] int32
    const int* __restrict__ dst,         // [E] int32
    float4* __restrict__ out,            // [E, 16] as float4
    int n_edges)
{
    const int j   = threadIdx.x & 7;     // float4 pair id within row
    const int row = threadIdx.x >> 3;    // edge slot within pass (0..31)
    const int stride = gridDim.x * EDGES_PER_CTA_ITER;

    for (int e = blockIdx.x * EDGES_PER_CTA_ITER + row; e < n_edges;
         e += stride) {
        // 8 adjacent threads read the same index -> single line, broadcast.
        const int s = __ldg(&src[e]);
        const int d = __ldg(&dst[e]);

        const float4* __restrict__ hs = h + (size_t)s * VEC_PER_ROW;
        const float4* __restrict__ hd = h + (size_t)d * VEC_PER_ROW;

        // Front-batched: 4 outstanding LDG.128 per thread (measured optimum).
        const float4 a0 = __ldg(hs + j);
        const float4 b0 = __ldg(hd + j);
        const float4 a1 = __ldg(hs + j + 8);
        const float4 b1 = __ldg(hd + j + 8);

        float4 r0, r1;
        r0.x = a0.x * b0.x; r0.y = a0.y * b0.y;
        r0.z = a0.z * b0.z; r0.w = a0.w * b0.w;
        r1.x = a1.x * b1.x; r1.y = a1.y * b1.y;
        r1.z = a1.z * b1.z; r1.w = a1.w * b1.w;

        float4* o = out + (size_t)e * VEC_PER_ROW + j;
        __stcs(o, r0);      // streaming: don't let output evict h from L2
        __stcs(o + 8, r1);
    }
}

extern "C" void kernel_launch(void* const* d_in, const int* in_sizes, int n_in,
                              void* d_out, int out_size) {
    const float4* h = (const float4*)d_in[0];
    const int* src = (const int*)d_in[1];
    const int* dst = (const int*)d_in[2];
    float4* out = (float4*)d_out;

    const int n_edges = in_sizes[1];  // E = 800000

    // Persistent: one wave. 152 SMs on GB300, occ 8 at 256 thr / 32 regs.
    // Use 148*8 = 1184 (works on 148- or 152-SM parts; <=1 wave either way).
    const int blocks = 1184;

    u_mul_v_kernel<<<blocks, THREADS>>>(h, src, dst, out, n_edges);
}

// round 16
// speedup vs baseline: 1.0926x; 1.0926x over previous
#include <cuda_runtime.h>
#include <stdint.h>

// z[e, :] = h[src[e], :] * h[dst[e], :]
// h: [N=50000, D=64] fp32 (12.8 MB, L2-resident), src/dst: [E=800000] int32,
// out: [E, 64] fp32.
//
// FINAL — best measured wall time (39.2us; reproduced 39.4, 39.7).
// The kernel is at the memory-system floor: ~165 MB/replay DRAM write drain
// @ ~4.2 TB/s plus random 256B-row gathers served from L2 (h fits in L2).
// Falsified levers (A/B measured, R5-R15): per-thread MLP scaling beyond 4
// outstanding gathers, L1 bypass, SMEM+TMA store staging, L2 evict_last
// pinning, store policy, 256-bit accesses (slower in replay steady state),
// persistent grid-stride launch (serializes per-warp memory batches).
//
// Config: flat launch, 8 threads/edge x 2 float4/thread (4 outstanding
// LDG.128 gathers, front-batched), __stcs streaming stores. Every warp
// access — index loads, gathers, stores — is full 128B lines.

static constexpr int D = 64;
static constexpr int VEC_PER_ROW = D / 4;   // 16 float4 per row
static constexpr int THREADS_PER_EDGE = 8;  // 2 float4 per thread

__global__ void __launch_bounds__(256, 8) u_mul_v_kernel(
    const float4* __restrict__ h,        // [N, 16] as float4
    const int* __restrict__ src,         // [E] int32
    const int* __restrict__ dst,         // [E] int32
    float4* __restrict__ out,            // [E, 16] as float4
    int n_edges)
{
    const int t = blockIdx.x * 256 + threadIdx.x;
    const int e = t >> 3;                // edge id
    const int j = t & 7;                 // float4 pair id within row
    if (e >= n_edges) return;

    // 8 adjacent threads read the same index -> single line, L1 broadcast.
    const int s = __ldg(&src[e]);
    const int d = __ldg(&dst[e]);

    const float4* __restrict__ hs = h + (size_t)s * VEC_PER_ROW;
    const float4* __restrict__ hd = h + (size_t)d * VEC_PER_ROW;

    // Two independent load pairs -> 4 outstanding LDG.128 per thread.
    const float4 a0 = __ldg(hs + j);
    const float4 b0 = __ldg(hd + j);
    const float4 a1 = __ldg(hs + j + 8);
    const float4 b1 = __ldg(hd + j + 8);

    float4 r0, r1;
    r0.x = a0.x * b0.x; r0.y = a0.y * b0.y;
    r0.z = a0.z * b0.z; r0.w = a0.w * b0.w;
    r1.x = a1.x * b1.x; r1.y = a1.y * b1.y;
    r1.z = a1.z * b1.z; r1.w = a1.w * b1.w;

    float4* o = out + (size_t)e * VEC_PER_ROW + j;
    __stcs(o, r0);          // streaming: don't let output evict h from L2
    __stcs(o + 8, r1);
}

extern "C" void kernel_launch(void* const* d_in, const int* in_sizes, int n_in,
                              void* d_out, int out_size) {
    const float4* h = (const float4*)d_in[0];
    const int* src = (const int*)d_in[1];
    const int* dst = (const int*)d_in[2];
    float4* out = (float4*)d_out;

    const int n_edges = in_sizes[1];  // E = 800000
    const long long total = (long long)n_edges * THREADS_PER_EDGE;
    const int threads = 256;
    const int blocks = (int)((total + threads - 1) / threads);

    u_mul_v_kernel<<<blocks, threads>>>(h, src, dst, out, n_edges);
}